// round 10
// baseline (speedup 1.0000x reference)
#include <cuda_runtime.h>
#include <cuda_bf16.h>
#include <cstdint>

// Problem constants
#define BATCH 16
#define NPTS  4096
#define MPTS  1024
#define C1    256
#define C2    512
#define CO    256
#define RTOT  65536
#define NZ    4
#define CHM   (MPTS / NZ)   // 256

// ---------------- scratch (static __device__ globals; no allocation) ----------
__device__ float  g_y  [(size_t)RTOT * CO];
__device__ float  g_y2 [(size_t)RTOT * CO];
__device__ float  g_Z  [(size_t)BATCH * MPTS * CO];     // P2 * W1a^T
__device__ unsigned short g_Bhi1a[CO * 512];
__device__ unsigned short g_Blo1a[CO * 512];
__device__ unsigned short g_Bhi1b[CO * 256];
__device__ unsigned short g_Blo1b[CO * 256];
__device__ unsigned short g_Bhi2 [CO * 256];
__device__ unsigned short g_Blo2 [CO * 256];
__device__ float  g_pd [(size_t)NZ * RTOT * 3];
__device__ int    g_pi [(size_t)NZ * RTOT * 3];
__device__ double g_stats[1024];

// ---------------- helpers ---------------------------------------------------------
__device__ __forceinline__ uint32_t smem_u32(const void* p) {
    uint32_t a;
    asm("{ .reg .u64 t; cvta.to.shared.u64 t, %1; cvt.u32.u64 %0, t; }" : "=r"(a) : "l"(p));
    return a;
}

__device__ __forceinline__ void cpa16(uint32_t s, const void* g) {
    asm volatile("cp.async.ca.shared.global [%0], [%1], 16;" :: "r"(s), "l"(g));
}
#define CP_COMMIT() asm volatile("cp.async.commit_group;" ::: "memory")
#define CP_WAIT0()  asm volatile("cp.async.wait_group 0;" ::: "memory")

#define LDSM4(r, addr) \
    asm volatile("ldmatrix.sync.aligned.m8n8.x4.shared.b16 {%0,%1,%2,%3}, [%4];" \
                 : "=r"((r)[0]), "=r"((r)[1]), "=r"((r)[2]), "=r"((r)[3]) : "r"(addr))

#define MMA16816(d, a, b0, b1) \
    asm volatile("mma.sync.aligned.m16n8k16.row.col.f32.bf16.bf16.f32 " \
                 "{%0,%1,%2,%3}, {%4,%5,%6,%7}, {%8,%9}, {%0,%1,%2,%3};" \
                 : "+f"((d)[0]), "+f"((d)[1]), "+f"((d)[2]), "+f"((d)[3]) \
                 : "r"((a)[0]), "r"((a)[1]), "r"((a)[2]), "r"((a)[3]), "r"(b0), "r"(b1))

__device__ __forceinline__ void split4(float4 v, uint2& hi, uint2& lo) {
    __nv_bfloat16 h0 = __float2bfloat16_rn(v.x);
    __nv_bfloat16 h1 = __float2bfloat16_rn(v.y);
    __nv_bfloat16 h2 = __float2bfloat16_rn(v.z);
    __nv_bfloat16 h3 = __float2bfloat16_rn(v.w);
    __nv_bfloat16 l0 = __float2bfloat16_rn(v.x - __bfloat162float(h0));
    __nv_bfloat16 l1 = __float2bfloat16_rn(v.y - __bfloat162float(h1));
    __nv_bfloat16 l2 = __float2bfloat16_rn(v.z - __bfloat162float(h2));
    __nv_bfloat16 l3 = __float2bfloat16_rn(v.w - __bfloat162float(h3));
    hi.x = (uint32_t)__bfloat16_as_ushort(h0) | ((uint32_t)__bfloat16_as_ushort(h1) << 16);
    hi.y = (uint32_t)__bfloat16_as_ushort(h2) | ((uint32_t)__bfloat16_as_ushort(h3) << 16);
    lo.x = (uint32_t)__bfloat16_as_ushort(l0) | ((uint32_t)__bfloat16_as_ushort(l1) << 16);
    lo.y = (uint32_t)__bfloat16_as_ushort(l2) | ((uint32_t)__bfloat16_as_ushort(l3) << 16);
}

// ---------------- setup: zero stats + split W1 (a|b) + split W2 -------------------
__global__ void setup_kernel(const float* __restrict__ W1, const float* __restrict__ W2,
                             unsigned short* __restrict__ BhiA, unsigned short* __restrict__ BloA,
                             unsigned short* __restrict__ BhiB, unsigned short* __restrict__ BloB,
                             unsigned short* __restrict__ Bhi2, unsigned short* __restrict__ Blo2,
                             double* __restrict__ stats) {
    int bid = blockIdx.x, tid = threadIdx.x;
    if (bid < 4) stats[bid * 256 + tid] = 0.0;
    if (bid < 768) {
        int idx = bid * 256 + tid;           // over 256*768
        int n = idx / 768, k = idx % 768;
        float v = W1[idx];
        __nv_bfloat16 hi = __float2bfloat16_rn(v);
        __nv_bfloat16 lo = __float2bfloat16_rn(v - __bfloat162float(hi));
        if (k < 512) {
            BhiA[n * 512 + k] = __bfloat16_as_ushort(hi);
            BloA[n * 512 + k] = __bfloat16_as_ushort(lo);
        } else {
            BhiB[n * 256 + (k - 512)] = __bfloat16_as_ushort(hi);
            BloB[n * 256 + (k - 512)] = __bfloat16_as_ushort(lo);
        }
    } else {
        int idx = (bid - 768) * 256 + tid;   // over 256*256
        float v = W2[idx];
        __nv_bfloat16 hi = __float2bfloat16_rn(v);
        __nv_bfloat16 lo = __float2bfloat16_rn(v - __bfloat162float(hi));
        Bhi2[idx] = __bfloat16_as_ushort(hi);
        Blo2[idx] = __bfloat16_as_ushort(lo);
    }
}

// ---------------- 3-NN partials: 2 queries per thread ------------------------------
__global__ void three_nn_part_kernel(const float* __restrict__ xyz1,
                                     const float* __restrict__ xyz2,
                                     float* __restrict__ pd, int* __restrict__ pi) {
    __shared__ float sx[CHM], sy[CHM], sz[CHM], s2[CHM];
    int b = blockIdx.y, ch = blockIdx.z;
    int tid = threadIdx.x;
    const float* p2 = xyz2 + ((size_t)b * MPTS + ch * CHM) * 3;
    {
        float px = p2[tid * 3 + 0], py = p2[tid * 3 + 1], pz = p2[tid * 3 + 2];
        sx[tid] = px; sy[tid] = py; sz[tid] = pz;
        s2[tid] = px * px + py * py + pz * pz;
    }
    __syncthreads();

    int n0 = blockIdx.x * 512 + tid;
    size_t rA = (size_t)b * NPTS + n0;
    size_t rB = rA + 256;
    float ax = xyz1[rA * 3 + 0], ay = xyz1[rA * 3 + 1], az = xyz1[rA * 3 + 2];
    float bx = xyz1[rB * 3 + 0], by = xyz1[rB * 3 + 1], bz = xyz1[rB * 3 + 2];

    float a0 = 1e30f, a1 = 1e30f, a2 = 1e30f;
    int   ia0 = 0, ia1 = 0, ia2 = 0;
    float b0 = 1e30f, b1 = 1e30f, b2 = 1e30f;
    int   ib0 = 0, ib1 = 0, ib2 = 0;
    #pragma unroll 4
    for (int j = 0; j < CHM; j++) {
        float px = sx[j], py = sy[j], pz = sz[j], pp = s2[j];
        float dA = fmaf(-2.f, fmaf(ax, px, fmaf(ay, py, az * pz)), pp);
        float dB = fmaf(-2.f, fmaf(bx, px, fmaf(by, py, bz * pz)), pp);
        if (dA < a0)      { a2 = a1; ia2 = ia1; a1 = a0; ia1 = ia0; a0 = dA; ia0 = j; }
        else if (dA < a1) { a2 = a1; ia2 = ia1; a1 = dA; ia1 = j; }
        else if (dA < a2) { a2 = dA; ia2 = j; }
        if (dB < b0)      { b2 = b1; ib2 = ib1; b1 = b0; ib1 = ib0; b0 = dB; ib0 = j; }
        else if (dB < b1) { b2 = b1; ib2 = ib1; b1 = dB; ib1 = j; }
        else if (dB < b2) { b2 = dB; ib2 = j; }
    }
    int base = ch * CHM;
    size_t oA = ((size_t)ch * RTOT + rA) * 3;
    pd[oA + 0] = a0;  pd[oA + 1] = a1;  pd[oA + 2] = a2;
    pi[oA + 0] = base + ia0; pi[oA + 1] = base + ia1; pi[oA + 2] = base + ia2;
    size_t oB = ((size_t)ch * RTOT + rB) * 3;
    pd[oB + 0] = b0;  pd[oB + 1] = b1;  pd[oB + 2] = b2;
    pi[oB + 0] = base + ib0; pi[oB + 1] = base + ib1; pi[oB + 2] = base + ib2;
}

// ---------------- split-bf16 HMMA GEMM: 128 threads, warp tile 64x64, 2 CTAs/SM ---
// Y(M x 256) = A(M x K) * B(256 x K)^T. A loaded via LDG.128 -> regs -> split -> STS
// (no staging round-trip). B pre-split bf16, cp.async double-buffered.
// CTA tile 128M x 128N (N halves across CTA pairs), 4 warps (2M x 2N), warp 64x64.
#define RS 40

#define SZ_AB    10240                // one matrix, one stage (128 * RS * 2)
#define OFF_AHI  0                    // [2 stages]
#define OFF_ALO  20480                // [2 stages]
#define OFF_BHI  40960                // [2 stages]
#define OFF_BLO  61440                // [2 stages]
#define OFF_IDX  81920                // 1536
#define OFF_SC   83456                // 1024
#define OFF_SH   84480                // 1024
#define OFF_SUM  85504                // 1024
#define OFF_SQ   86528                // 1024
#define SM_TOTAL 87552

template<int K, int BNFIN, int GATHER, int STATS>
__global__ void __launch_bounds__(128, 2)
gemm_kernel(const float* __restrict__ Aptr,
            const unsigned short* __restrict__ BhiG,
            const unsigned short* __restrict__ BloG,
            const float* __restrict__ pd,
            const int* __restrict__ pi,
            const float* __restrict__ Z,
            const double* __restrict__ statsIn,
            const float* __restrict__ gvec,
            const float* __restrict__ betavec,
            float* __restrict__ Y,
            double* __restrict__ statsOut) {
    constexpr int KCH = K / 32;
    extern __shared__ char sm[];
    uint32_t sb = smem_u32(sm);

    int tid = threadIdx.x, lane = tid & 31, wid = tid >> 5;
    int wm = wid & 1, wn = wid >> 1;                  // 2M x 2N warps
    int rbase = (blockIdx.x >> 1) * 128;
    int nbase = (blockIdx.x & 1) * 128;

    const unsigned short* Bhi = BhiG + (size_t)nbase * K;
    const unsigned short* Blo = BloG + (size_t)nbase * K;
    const float* Ab = Aptr + (size_t)rbase * K;

    if (GATHER) {
        // in-prologue 3-NN merge for this CTA's 128 rows
        int r = rbase + tid;
        float d0 = 1e30f, d1 = 1e30f, d2v = 1e30f;
        int   i0 = 0, i1 = 0, i2 = 0;
        #pragma unroll
        for (int ch = 0; ch < NZ; ch++) {
            size_t o = ((size_t)ch * RTOT + r) * 3;
            #pragma unroll
            for (int k = 0; k < 3; k++) {
                float d = pd[o + k];
                int   ii = pi[o + k];
                if (d < d0)        { d2v = d1; i2 = i1; d1 = d0; i1 = i0; d0 = d; i0 = ii; }
                else if (d < d1)   { d2v = d1; i2 = i1; d1 = d;  i1 = ii; }
                else if (d < d2v)  { d2v = d;  i2 = ii; }
            }
        }
        int* sidx = (int*)(sm + OFF_IDX);
        sidx[tid * 3 + 0] = i0;
        sidx[tid * 3 + 1] = i1;
        sidx[tid * 3 + 2] = i2;
    }
    if (BNFIN) {
        #pragma unroll
        for (int h = 0; h < 2; h++) {
            int c = tid + h * 128;
            double mean = statsIn[c] * (1.0 / RTOT);
            double var  = statsIn[CO + c] * (1.0 / RTOT) - mean * mean;
            float sc = gvec[c] * rsqrtf((float)var + 1e-5f);
            ((float*)(sm + OFF_SC))[c] = sc;
            ((float*)(sm + OFF_SH))[c] = betavec[c] - (float)mean * sc;
        }
    }
    if (STATS) {
        #pragma unroll
        for (int h = 0; h < 2; h++) {
            ((float*)(sm + OFF_SUM))[tid + h * 128] = 0.f;
            ((float*)(sm + OFF_SQ))[tid + h * 128]  = 0.f;
        }
    }
    __syncthreads();

    // --- B tiles via cp.async: per chunk per matrix 512 16B slots / 128 thr = 4 each
    auto cp_B = [&](int c, int s) {
        int k0 = c * 32;
        #pragma unroll
        for (int it = 0; it < 4; it++) {
            int slot = it * 128 + tid;
            int row = slot >> 2, q = slot & 3;
            uint32_t d = (uint32_t)(row * RS + q * 8) * 2;
            size_t go = (size_t)row * K + k0 + q * 8;
            cpa16(sb + OFF_BHI + s * SZ_AB + d, Bhi + go);
            cpa16(sb + OFF_BLO + s * SZ_AB + d, Blo + go);
        }
        CP_COMMIT();
    };

    // --- A tile via LDG.128 into regs (8 float4/thread)
    float4 pf[8];
    auto ldg_A = [&](int c) {
        int k0 = c * 32;
        #pragma unroll
        for (int it = 0; it < 8; it++) {
            int slot = it * 128 + tid;
            int row = slot >> 3, q = slot & 7;
            pf[it] = *(const float4*)(Ab + (size_t)row * K + k0 + q * 4);
        }
    };

    auto convert_A = [&](int c, int s) {
        int k0 = c * 32;
        #pragma unroll
        for (int it = 0; it < 8; it++) {
            int slot = it * 128 + tid;
            int row = slot >> 3, q = slot & 7;
            float4 v = pf[it];
            if (BNFIN) {
                const float* sc = (const float*)(sm + OFF_SC) + k0 + q * 4;
                const float* sh = (const float*)(sm + OFF_SH) + k0 + q * 4;
                v.x = fmaxf(v.x * sc[0] + sh[0], 0.f);
                v.y = fmaxf(v.y * sc[1] + sh[1], 0.f);
                v.z = fmaxf(v.z * sc[2] + sh[2], 0.f);
                v.w = fmaxf(v.w * sc[3] + sh[3], 0.f);
            }
            uint2 hi, lo;
            split4(v, hi, lo);
            uint32_t d = (uint32_t)(row * RS + q * 4) * 2;
            *(uint2*)(sm + OFF_AHI + s * SZ_AB + d) = hi;
            *(uint2*)(sm + OFF_ALO + s * SZ_AB + d) = lo;
        }
    };

    cp_B(0, 0);
    ldg_A(0);
    convert_A(0, 0);
    CP_WAIT0();
    __syncthreads();

    float acc[4][8][4] = {};   // 4 m16 x 8 n8 x 4 = 128 regs

    for (int c = 0; c < KCH; c++) {
        int s = c & 1;
        if (c + 1 < KCH) {
            cp_B(c + 1, 1 - s);
            ldg_A(c + 1);
        }

        uint32_t sAhi = sb + OFF_AHI + s * SZ_AB;
        uint32_t sAlo = sb + OFF_ALO + s * SZ_AB;
        uint32_t sBhi = sb + OFF_BHI + s * SZ_AB;
        uint32_t sBlo = sb + OFF_BLO + s * SZ_AB;

        #pragma unroll
        for (int ks = 0; ks < 2; ks++) {
            int arow = wm * 64 + (lane & 15);
            int akoff = ks * 16 + (lane >> 4) * 8;
            int brow = wn * 64 + (lane & 7) + ((lane >> 4) & 1) * 8;
            int bkoff = ks * 16 + ((lane >> 3) & 1) * 8;

            uint32_t ah[4][4], bh[4][4];
            #pragma unroll
            for (int mi = 0; mi < 4; mi++)
                LDSM4(ah[mi], sAhi + (uint32_t)((arow + mi * 16) * RS + akoff) * 2);
            #pragma unroll
            for (int jj = 0; jj < 4; jj++)
                LDSM4(bh[jj], sBhi + (uint32_t)((brow + jj * 16) * RS + bkoff) * 2);

            // hh
            #pragma unroll
            for (int mi = 0; mi < 4; mi++)
                #pragma unroll
                for (int jj = 0; jj < 4; jj++) {
                    MMA16816(acc[mi][jj * 2 + 0], ah[mi], bh[jj][0], bh[jj][1]);
                    MMA16816(acc[mi][jj * 2 + 1], ah[mi], bh[jj][2], bh[jj][3]);
                }
            // hl (Ahi x Blo) — bl loaded here, freed after
            {
                uint32_t bl[4][4];
                #pragma unroll
                for (int jj = 0; jj < 4; jj++)
                    LDSM4(bl[jj], sBlo + (uint32_t)((brow + jj * 16) * RS + bkoff) * 2);
                #pragma unroll
                for (int mi = 0; mi < 4; mi++)
                    #pragma unroll
                    for (int jj = 0; jj < 4; jj++) {
                        MMA16816(acc[mi][jj * 2 + 0], ah[mi], bl[jj][0], bl[jj][1]);
                        MMA16816(acc[mi][jj * 2 + 1], ah[mi], bl[jj][2], bl[jj][3]);
                    }
            }
            // lh (Alo x Bhi) — ah dead, al loaded here
            {
                uint32_t al[4][4];
                #pragma unroll
                for (int mi = 0; mi < 4; mi++)
                    LDSM4(al[mi], sAlo + (uint32_t)((arow + mi * 16) * RS + akoff) * 2);
                #pragma unroll
                for (int mi = 0; mi < 4; mi++)
                    #pragma unroll
                    for (int jj = 0; jj < 4; jj++) {
                        MMA16816(acc[mi][jj * 2 + 0], al[mi], bh[jj][0], bh[jj][1]);
                        MMA16816(acc[mi][jj * 2 + 1], al[mi], bh[jj][2], bh[jj][3]);
                    }
            }
        }
        if (c + 1 < KCH) {
            convert_A(c + 1, 1 - s);
            CP_WAIT0();
        }
        __syncthreads();
    }

    // ---- epilogue ----
    if (GATHER) {
        int b = rbase >> 12;
        const float* Zb = Z + (size_t)b * MPTS * CO;
        const float third = 1.0f / 3.0f;
        const int* idxsm = (const int*)(sm + OFF_IDX);
        #pragma unroll
        for (int mi = 0; mi < 4; mi++) {
            #pragma unroll
            for (int r2 = 0; r2 < 2; r2++) {
                int lrow = wm * 64 + (lane >> 2) + mi * 16 + r2 * 8;
                const int* si = idxsm + lrow * 3;
                const float* z0 = Zb + (size_t)si[0] * CO;
                const float* z1 = Zb + (size_t)si[1] * CO;
                const float* z2 = Zb + (size_t)si[2] * CO;
                #pragma unroll
                for (int nb = 0; nb < 8; nb++) {
                    int col = nbase + wn * 64 + nb * 8 + (lane & 3) * 2;
                    float2 q0 = *(const float2*)(z0 + col);
                    float2 q1 = *(const float2*)(z1 + col);
                    float2 q2 = *(const float2*)(z2 + col);
                    acc[mi][nb][r2 * 2 + 0] += (q0.x + q1.x + q2.x) * third;
                    acc[mi][nb][r2 * 2 + 1] += (q0.y + q1.y + q2.y) * third;
                }
            }
        }
    }

    int rr = rbase + wm * 64 + (lane >> 2);
    int cc0 = nbase + wn * 64 + (lane & 3) * 2;
    #pragma unroll
    for (int mi = 0; mi < 4; mi++) {
        #pragma unroll
        for (int nb = 0; nb < 8; nb++) {
            int col = cc0 + nb * 8;
            float* a = acc[mi][nb];
            *(float2*)(Y + (size_t)(rr + mi * 16)     * CO + col) = make_float2(a[0], a[1]);
            *(float2*)(Y + (size_t)(rr + mi * 16 + 8) * CO + col) = make_float2(a[2], a[3]);
        }
    }
    if (STATS) {
        float* ssum = (float*)(sm + OFF_SUM);
        float* ssq  = (float*)(sm + OFF_SQ);
        #pragma unroll
        for (int nb = 0; nb < 8; nb++) {
            int col = cc0 + nb * 8;
            float s0 = 0.f, s1 = 0.f, q0 = 0.f, q1 = 0.f;
            #pragma unroll
            for (int mi = 0; mi < 4; mi++) {
                float* a = acc[mi][nb];
                s0 += a[0] + a[2];
                s1 += a[1] + a[3];
                q0 += a[0] * a[0] + a[2] * a[2];
                q1 += a[1] * a[1] + a[3] * a[3];
            }
            atomicAdd(&ssum[col], s0);
            atomicAdd(&ssq[col],  q0);
            atomicAdd(&ssum[col + 1], s1);
            atomicAdd(&ssq[col + 1],  q1);
        }
        __syncthreads();
        {
            int col = nbase + tid;
            atomicAdd(&statsOut[col],      (double)ssum[col]);
            atomicAdd(&statsOut[CO + col], (double)ssq[col]);
        }
    }
}

// ---------------- final BN (in-block finalize) + ReLU + transpose ------------------
__global__ void bn_relu_tr_kernel(const float* __restrict__ y,
                                  const double* __restrict__ stats,
                                  const float* __restrict__ g, const float* __restrict__ beta,
                                  float* __restrict__ out) {
    __shared__ float t[32][33];
    __shared__ float sscale[32], sshift[32];
    int b = blockIdx.z;
    int n0 = blockIdx.x * 32, c0 = blockIdx.y * 32;
    if (threadIdx.y == 0) {
        int c = c0 + threadIdx.x;
        double mean = stats[c] * (1.0 / RTOT);
        double var  = stats[CO + c] * (1.0 / RTOT) - mean * mean;
        float sc = g[c] * rsqrtf((float)var + 1e-5f);
        sscale[threadIdx.x] = sc;
        sshift[threadIdx.x] = beta[c] - (float)mean * sc;
    }
    __syncthreads();
    int n = n0 + threadIdx.y, c = c0 + threadIdx.x;
    float v = y[((size_t)b * NPTS + n) * CO + c];
    v = fmaxf(v * sscale[threadIdx.x] + sshift[threadIdx.x], 0.f);
    t[threadIdx.y][threadIdx.x] = v;
    __syncthreads();
    out[((size_t)b * CO + c0 + threadIdx.y) * NPTS + n0 + threadIdx.x] = t[threadIdx.x][threadIdx.y];
}

// ---------------- launch -----------------------------------------------------------
extern "C" void kernel_launch(void* const* d_in, const int* in_sizes, int n_in,
                              void* d_out, int out_size) {
    const float* xyz1    = (const float*)d_in[0];
    const float* xyz2    = (const float*)d_in[1];
    const float* points1 = (const float*)d_in[2];
    const float* points2 = (const float*)d_in[3];
    const float* W1      = (const float*)d_in[4];
    const float* g1      = (const float*)d_in[6];
    const float* beta1   = (const float*)d_in[7];
    const float* W2      = (const float*)d_in[8];
    const float* g2      = (const float*)d_in[10];
    const float* beta2   = (const float*)d_in[11];
    float* out = (float*)d_out;

    float *y, *y2, *Z, *pd;
    unsigned short *Bhi1a, *Blo1a, *Bhi1b, *Blo1b, *Bhi2, *Blo2;
    int *pi;
    double* stats;
    cudaGetSymbolAddress((void**)&y, g_y);
    cudaGetSymbolAddress((void**)&y2, g_y2);
    cudaGetSymbolAddress((void**)&Z, g_Z);
    cudaGetSymbolAddress((void**)&Bhi1a, g_Bhi1a);
    cudaGetSymbolAddress((void**)&Blo1a, g_Blo1a);
    cudaGetSymbolAddress((void**)&Bhi1b, g_Bhi1b);
    cudaGetSymbolAddress((void**)&Blo1b, g_Blo1b);
    cudaGetSymbolAddress((void**)&Bhi2, g_Bhi2);
    cudaGetSymbolAddress((void**)&Blo2, g_Blo2);
    cudaGetSymbolAddress((void**)&pd, g_pd);
    cudaGetSymbolAddress((void**)&pi, g_pi);
    cudaGetSymbolAddress((void**)&stats, g_stats);

    cudaFuncSetAttribute(gemm_kernel<512,0,0,0>, cudaFuncAttributeMaxDynamicSharedMemorySize, SM_TOTAL);
    cudaFuncSetAttribute(gemm_kernel<256,0,1,1>, cudaFuncAttributeMaxDynamicSharedMemorySize, SM_TOTAL);
    cudaFuncSetAttribute(gemm_kernel<256,1,0,1>, cudaFuncAttributeMaxDynamicSharedMemorySize, SM_TOTAL);

    // setup: zero stats + split W1/W2
    setup_kernel<<<1024, 256>>>(W1, W2, Bhi1a, Blo1a, Bhi1b, Blo1b, Bhi2, Blo2, stats);

    // 3-NN partials (2 queries per thread)
    three_nn_part_kernel<<<dim3(NPTS / 512, BATCH, NZ), 256>>>(xyz1, xyz2, pd, pi);

    // Z = points2 * W1a^T   (M = 16*1024, K = 512)
    gemm_kernel<512,0,0,0><<<(BATCH * MPTS / 128) * 2, 128, SM_TOTAL>>>(
        points2, Bhi1a, Blo1a, nullptr, nullptr, nullptr, nullptr, nullptr, nullptr, Z, nullptr);

    // Y1 = points1 * W1b^T + gather3(Z)/3 ; in-prologue NN merge; stats
    gemm_kernel<256,0,1,1><<<(RTOT / 128) * 2, 128, SM_TOTAL>>>(
        points1, Bhi1b, Blo1b, pd, pi, Z, nullptr, nullptr, nullptr, y, stats);

    // Y2 = relu(bn(Y1)) * W2^T ; in-prologue finalize from stats1 ; stats
    gemm_kernel<256,1,0,1><<<(RTOT / 128) * 2, 128, SM_TOTAL>>>(
        y, Bhi2, Blo2, nullptr, nullptr, nullptr, stats, g1, beta1, y2, stats + 512);

    // final BN (in-block finalize from stats2) + ReLU + transpose
    bn_relu_tr_kernel<<<dim3(NPTS / 32, CO / 32, BATCH), dim3(32, 32)>>>(
        y2, stats + 512, g2, beta2, out);
}

// round 11
// speedup vs baseline: 1.2384x; 1.2384x over previous
#include <cuda_runtime.h>
#include <cuda_fp16.h>
#include <cstdint>

// Problem constants
#define BATCH 16
#define NPTS  4096
#define MPTS  1024
#define C1    256
#define C2    512
#define CO    256
#define RTOT  65536
#define NZ    4
#define CHM   (MPTS / NZ)   // 256

// ---------------- scratch (static __device__ globals; no allocation) ----------
__device__ float  g_y  [(size_t)RTOT * CO];
__device__ float  g_y2 [(size_t)RTOT * CO];
__device__ float  g_Z  [(size_t)BATCH * MPTS * CO];     // P2 * W1a^T
__device__ unsigned short g_Bhi1a[CO * 512];
__device__ unsigned short g_Blo1a[CO * 512];
__device__ unsigned short g_Bhi1b[CO * 256];
__device__ unsigned short g_Blo1b[CO * 256];
__device__ unsigned short g_Bhi2 [CO * 256];
__device__ unsigned short g_Blo2 [CO * 256];
__device__ float  g_pd [(size_t)NZ * RTOT * 3];
__device__ int    g_pi [(size_t)NZ * RTOT * 3];
__device__ double g_stats[1024];

// ---------------- helpers ---------------------------------------------------------
__device__ __forceinline__ uint32_t smem_u32(const void* p) {
    uint32_t a;
    asm("{ .reg .u64 t; cvta.to.shared.u64 t, %1; cvt.u32.u64 %0, t; }" : "=r"(a) : "l"(p));
    return a;
}

__device__ __forceinline__ void cpa16(uint32_t s, const void* g) {
    asm volatile("cp.async.ca.shared.global [%0], [%1], 16;" :: "r"(s), "l"(g));
}
#define CP_COMMIT() asm volatile("cp.async.commit_group;" ::: "memory")
#define CP_WAIT0()  asm volatile("cp.async.wait_group 0;" ::: "memory")

#define LDSM4(r, addr) \
    asm volatile("ldmatrix.sync.aligned.m8n8.x4.shared.b16 {%0,%1,%2,%3}, [%4];" \
                 : "=r"((r)[0]), "=r"((r)[1]), "=r"((r)[2]), "=r"((r)[3]) : "r"(addr))

#define MMA16816(d, a, b0, b1) \
    asm volatile("mma.sync.aligned.m16n8k16.row.col.f32.f16.f16.f32 " \
                 "{%0,%1,%2,%3}, {%4,%5,%6,%7}, {%8,%9}, {%0,%1,%2,%3};" \
                 : "+f"((d)[0]), "+f"((d)[1]), "+f"((d)[2]), "+f"((d)[3]) \
                 : "r"((a)[0]), "r"((a)[1]), "r"((a)[2]), "r"((a)[3]), "r"(b0), "r"(b1))

// fp32x4 -> fp16x4 (single rounding; A operand)
__device__ __forceinline__ uint2 cvt4h(float4 v) {
    __half2 p0 = __floats2half2_rn(v.x, v.y);
    __half2 p1 = __floats2half2_rn(v.z, v.w);
    uint2 r;
    r.x = *(uint32_t*)&p0;
    r.y = *(uint32_t*)&p1;
    return r;
}

// ---------------- setup: zero stats + split W1 (a|b) + split W2 (fp16 hi/lo) ------
__global__ void setup_kernel(const float* __restrict__ W1, const float* __restrict__ W2,
                             unsigned short* __restrict__ BhiA, unsigned short* __restrict__ BloA,
                             unsigned short* __restrict__ BhiB, unsigned short* __restrict__ BloB,
                             unsigned short* __restrict__ Bhi2, unsigned short* __restrict__ Blo2,
                             double* __restrict__ stats) {
    int bid = blockIdx.x, tid = threadIdx.x;
    if (bid < 4) stats[bid * 256 + tid] = 0.0;
    if (bid < 768) {
        int idx = bid * 256 + tid;           // over 256*768
        int n = idx / 768, k = idx % 768;
        float v = W1[idx];
        __half hi = __float2half_rn(v);
        __half lo = __float2half_rn(v - __half2float(hi));
        if (k < 512) {
            BhiA[n * 512 + k] = __half_as_ushort(hi);
            BloA[n * 512 + k] = __half_as_ushort(lo);
        } else {
            BhiB[n * 256 + (k - 512)] = __half_as_ushort(hi);
            BloB[n * 256 + (k - 512)] = __half_as_ushort(lo);
        }
    } else {
        int idx = (bid - 768) * 256 + tid;   // over 256*256
        float v = W2[idx];
        __half hi = __float2half_rn(v);
        __half lo = __float2half_rn(v - __half2float(hi));
        Bhi2[idx] = __half_as_ushort(hi);
        Blo2[idx] = __half_as_ushort(lo);
    }
}

// ---------------- 3-NN partials: 2 queries per thread ------------------------------
__global__ void three_nn_part_kernel(const float* __restrict__ xyz1,
                                     const float* __restrict__ xyz2,
                                     float* __restrict__ pd, int* __restrict__ pi) {
    __shared__ float sx[CHM], sy[CHM], sz[CHM], s2[CHM];
    int b = blockIdx.y, ch = blockIdx.z;
    int tid = threadIdx.x;
    const float* p2 = xyz2 + ((size_t)b * MPTS + ch * CHM) * 3;
    {
        float px = p2[tid * 3 + 0], py = p2[tid * 3 + 1], pz = p2[tid * 3 + 2];
        sx[tid] = px; sy[tid] = py; sz[tid] = pz;
        s2[tid] = px * px + py * py + pz * pz;
    }
    __syncthreads();

    int n0 = blockIdx.x * 512 + tid;
    size_t rA = (size_t)b * NPTS + n0;
    size_t rB = rA + 256;
    float ax = xyz1[rA * 3 + 0], ay = xyz1[rA * 3 + 1], az = xyz1[rA * 3 + 2];
    float bx = xyz1[rB * 3 + 0], by = xyz1[rB * 3 + 1], bz = xyz1[rB * 3 + 2];

    float a0 = 1e30f, a1 = 1e30f, a2 = 1e30f;
    int   ia0 = 0, ia1 = 0, ia2 = 0;
    float b0 = 1e30f, b1 = 1e30f, b2 = 1e30f;
    int   ib0 = 0, ib1 = 0, ib2 = 0;
    #pragma unroll 4
    for (int j = 0; j < CHM; j++) {
        float px = sx[j], py = sy[j], pz = sz[j], pp = s2[j];
        float dA = fmaf(-2.f, fmaf(ax, px, fmaf(ay, py, az * pz)), pp);
        float dB = fmaf(-2.f, fmaf(bx, px, fmaf(by, py, bz * pz)), pp);
        if (dA < a0)      { a2 = a1; ia2 = ia1; a1 = a0; ia1 = ia0; a0 = dA; ia0 = j; }
        else if (dA < a1) { a2 = a1; ia2 = ia1; a1 = dA; ia1 = j; }
        else if (dA < a2) { a2 = dA; ia2 = j; }
        if (dB < b0)      { b2 = b1; ib2 = ib1; b1 = b0; ib1 = ib0; b0 = dB; ib0 = j; }
        else if (dB < b1) { b2 = b1; ib2 = ib1; b1 = dB; ib1 = j; }
        else if (dB < b2) { b2 = dB; ib2 = j; }
    }
    int base = ch * CHM;
    size_t oA = ((size_t)ch * RTOT + rA) * 3;
    pd[oA + 0] = a0;  pd[oA + 1] = a1;  pd[oA + 2] = a2;
    pi[oA + 0] = base + ia0; pi[oA + 1] = base + ia1; pi[oA + 2] = base + ia2;
    size_t oB = ((size_t)ch * RTOT + rB) * 3;
    pd[oB + 0] = b0;  pd[oB + 1] = b1;  pd[oB + 2] = b2;
    pi[oB + 0] = base + ib0; pi[oB + 1] = base + ib1; pi[oB + 2] = base + ib2;
}

// ---------------- fp16 2-product HMMA GEMM, 2 CTAs/SM -----------------------------
// Y(M x 256) = A(M x K) * B(256 x K)^T ; A rounded once to fp16 in-kernel,
// B = W split fp16 hi+lo (exact). C = Ah*Bh + Ah*Bl  (2 MMAs per k16 step).
// CTA tile 128M x 128N (N halves across CTA pairs), 8 warps (2M x 4N), warp 64x32.
#define RS    40
#define RSRAW 36

#define SZ_BUF   10240                // one matrix, one stage (128 * RS * 2B)
#define OFF_AHI  0                    // 2 stages -> 20480
#define OFF_BHI  20480                // 2 stages -> 20480
#define OFF_BLO  40960                // 2 stages -> 20480
#define OFF_RAW  61440                // 18432
#define OFF_IDX  79872                // 1536
#define OFF_SC   81408                // 1024
#define OFF_SH   82432                // 1024
#define OFF_SUM  83456                // 1024
#define OFF_SQ   84480                // 1024
#define SM_TOTAL 85504

template<int K, int BNFIN, int GATHER, int STATS>
__global__ void __launch_bounds__(256, 2)
gemm_kernel(const float* __restrict__ Aptr,
            const unsigned short* __restrict__ BhiG,
            const unsigned short* __restrict__ BloG,
            const float* __restrict__ pd,
            const int* __restrict__ pi,
            const float* __restrict__ Z,
            const double* __restrict__ statsIn,
            const float* __restrict__ gvec,
            const float* __restrict__ betavec,
            float* __restrict__ Y,
            double* __restrict__ statsOut) {
    constexpr int KCH = K / 32;
    extern __shared__ char sm[];
    uint32_t sb = smem_u32(sm);

    int tid = threadIdx.x, lane = tid & 31, wid = tid >> 5;
    int wm = wid & 1, wn = wid >> 1;                  // 2M x 4N warps
    int rbase = (blockIdx.x >> 1) * 128;
    int nbase = (blockIdx.x & 1) * 128;

    const unsigned short* Bhi = BhiG + (size_t)nbase * K;
    const unsigned short* Blo = BloG + (size_t)nbase * K;

    if (GATHER) {
        if (tid < 128) {
            int r = rbase + tid;
            float d0 = 1e30f, d1 = 1e30f, d2v = 1e30f;
            int   i0 = 0, i1 = 0, i2 = 0;
            #pragma unroll
            for (int ch = 0; ch < NZ; ch++) {
                size_t o = ((size_t)ch * RTOT + r) * 3;
                #pragma unroll
                for (int k = 0; k < 3; k++) {
                    float d = pd[o + k];
                    int   ii = pi[o + k];
                    if (d < d0)        { d2v = d1; i2 = i1; d1 = d0; i1 = i0; d0 = d; i0 = ii; }
                    else if (d < d1)   { d2v = d1; i2 = i1; d1 = d;  i1 = ii; }
                    else if (d < d2v)  { d2v = d;  i2 = ii; }
                }
            }
            int* sidx = (int*)(sm + OFF_IDX);
            sidx[tid * 3 + 0] = i0;
            sidx[tid * 3 + 1] = i1;
            sidx[tid * 3 + 2] = i2;
        }
    }
    if (BNFIN) {
        double mean = statsIn[tid] * (1.0 / RTOT);
        double var  = statsIn[CO + tid] * (1.0 / RTOT) - mean * mean;
        float sc = gvec[tid] * rsqrtf((float)var + 1e-5f);
        ((float*)(sm + OFF_SC))[tid] = sc;
        ((float*)(sm + OFF_SH))[tid] = betavec[tid] - (float)mean * sc;
    }
    if (STATS) {
        ((float*)(sm + OFF_SUM))[tid] = 0.f;
        ((float*)(sm + OFF_SQ))[tid]  = 0.f;
    }
    __syncthreads();

    auto cp_chunk = [&](int c, int s) {
        int k0 = c * 32;
        #pragma unroll
        for (int it = 0; it < 2; it++) {       // B: 512 16B slots per matrix
            int slot = it * 256 + tid;
            int row = slot >> 2, q = slot & 3;
            uint32_t d = (uint32_t)(row * RS + q * 8) * 2;
            size_t go = (size_t)row * K + k0 + q * 8;
            cpa16(sb + OFF_BHI + s * SZ_BUF + d, Bhi + go);
            cpa16(sb + OFF_BLO + s * SZ_BUF + d, Blo + go);
        }
        #pragma unroll
        for (int it = 0; it < 4; it++) {       // A raw fp32: 1024 16B slots
            int slot = it * 256 + tid;
            int row = slot >> 3, q = slot & 7;
            uint32_t d = sb + OFF_RAW + (uint32_t)(row * RSRAW + q * 4) * 4;
            cpa16(d, Aptr + (size_t)(rbase + row) * K + k0 + q * 4);
        }
        CP_COMMIT();
    };

    auto convert_chunk = [&](int c, int s) {
        int k0 = c * 32;
        #pragma unroll
        for (int it = 0; it < 4; it++) {
            int slot = it * 256 + tid;
            int row = slot >> 3, q = slot & 7;
            float4 v = *(const float4*)(sm + OFF_RAW + (uint32_t)(row * RSRAW + q * 4) * 4);
            if (BNFIN) {
                const float* sc = (const float*)(sm + OFF_SC) + k0 + q * 4;
                const float* sh = (const float*)(sm + OFF_SH) + k0 + q * 4;
                v.x = fmaxf(v.x * sc[0] + sh[0], 0.f);
                v.y = fmaxf(v.y * sc[1] + sh[1], 0.f);
                v.z = fmaxf(v.z * sc[2] + sh[2], 0.f);
                v.w = fmaxf(v.w * sc[3] + sh[3], 0.f);
            }
            uint2 h = cvt4h(v);
            *(uint2*)(sm + OFF_AHI + s * SZ_BUF + (uint32_t)(row * RS + q * 4) * 2) = h;
        }
    };

    cp_chunk(0, 0);
    CP_WAIT0();
    convert_chunk(0, 0);
    __syncthreads();

    float acc[4][4][4] = {};   // 4 m16 x 4 n8 x 4 = 64 regs

    for (int c = 0; c < KCH; c++) {
        int s = c & 1;
        if (c + 1 < KCH) cp_chunk(c + 1, 1 - s);

        uint32_t sAhi = sb + OFF_AHI + s * SZ_BUF;
        uint32_t sBhi = sb + OFF_BHI + s * SZ_BUF;
        uint32_t sBlo = sb + OFF_BLO + s * SZ_BUF;

        #pragma unroll
        for (int ks = 0; ks < 2; ks++) {
            int arow = wm * 64 + (lane & 15);
            int akoff = ks * 16 + (lane >> 4) * 8;
            int brow = wn * 32 + (lane & 7) + ((lane >> 4) & 1) * 8;
            int bkoff = ks * 16 + ((lane >> 3) & 1) * 8;

            uint32_t ah[4][4], bh[2][4];
            #pragma unroll
            for (int mi = 0; mi < 4; mi++)
                LDSM4(ah[mi], sAhi + (uint32_t)((arow + mi * 16) * RS + akoff) * 2);
            #pragma unroll
            for (int jj = 0; jj < 2; jj++)
                LDSM4(bh[jj], sBhi + (uint32_t)((brow + jj * 16) * RS + bkoff) * 2);

            // hh: Ah * Wh (16 independent MMAs)
            #pragma unroll
            for (int mi = 0; mi < 4; mi++)
                #pragma unroll
                for (int jj = 0; jj < 2; jj++) {
                    MMA16816(acc[mi][jj * 2 + 0], ah[mi], bh[jj][0], bh[jj][1]);
                    MMA16816(acc[mi][jj * 2 + 1], ah[mi], bh[jj][2], bh[jj][3]);
                }
            // hl: Ah * Wl
            uint32_t bl[2][4];
            #pragma unroll
            for (int jj = 0; jj < 2; jj++)
                LDSM4(bl[jj], sBlo + (uint32_t)((brow + jj * 16) * RS + bkoff) * 2);
            #pragma unroll
            for (int mi = 0; mi < 4; mi++)
                #pragma unroll
                for (int jj = 0; jj < 2; jj++) {
                    MMA16816(acc[mi][jj * 2 + 0], ah[mi], bl[jj][0], bl[jj][1]);
                    MMA16816(acc[mi][jj * 2 + 1], ah[mi], bl[jj][2], bl[jj][3]);
                }
        }
        if (c + 1 < KCH) {
            CP_WAIT0();
            convert_chunk(c + 1, 1 - s);
        }
        __syncthreads();
    }

    // ---- epilogue ----
    if (GATHER) {
        int b = rbase >> 12;
        const float* Zb = Z + (size_t)b * MPTS * CO;
        const float third = 1.0f / 3.0f;
        const int* idxsm = (const int*)(sm + OFF_IDX);
        #pragma unroll
        for (int mi = 0; mi < 4; mi++) {
            #pragma unroll
            for (int r2 = 0; r2 < 2; r2++) {
                int lrow = wm * 64 + (lane >> 2) + mi * 16 + r2 * 8;
                const int* si = idxsm + lrow * 3;
                const float* z0 = Zb + (size_t)si[0] * CO;
                const float* z1 = Zb + (size_t)si[1] * CO;
                const float* z2 = Zb + (size_t)si[2] * CO;
                #pragma unroll
                for (int nb = 0; nb < 4; nb++) {
                    int col = nbase + wn * 32 + nb * 8 + (lane & 3) * 2;
                    float2 q0 = *(const float2*)(z0 + col);
                    float2 q1 = *(const float2*)(z1 + col);
                    float2 q2 = *(const float2*)(z2 + col);
                    acc[mi][nb][r2 * 2 + 0] += (q0.x + q1.x + q2.x) * third;
                    acc[mi][nb][r2 * 2 + 1] += (q0.y + q1.y + q2.y) * third;
                }
            }
        }
    }

    int rr = rbase + wm * 64 + (lane >> 2);
    int cc0 = nbase + wn * 32 + (lane & 3) * 2;
    #pragma unroll
    for (int mi = 0; mi < 4; mi++) {
        #pragma unroll
        for (int nb = 0; nb < 4; nb++) {
            int col = cc0 + nb * 8;
            float* a = acc[mi][nb];
            *(float2*)(Y + (size_t)(rr + mi * 16)     * CO + col) = make_float2(a[0], a[1]);
            *(float2*)(Y + (size_t)(rr + mi * 16 + 8) * CO + col) = make_float2(a[2], a[3]);
        }
    }
    if (STATS) {
        float* ssum = (float*)(sm + OFF_SUM);
        float* ssq  = (float*)(sm + OFF_SQ);
        #pragma unroll
        for (int nb = 0; nb < 4; nb++) {
            int col = cc0 + nb * 8;
            float s0 = 0.f, s1 = 0.f, q0 = 0.f, q1 = 0.f;
            #pragma unroll
            for (int mi = 0; mi < 4; mi++) {
                float* a = acc[mi][nb];
                s0 += a[0] + a[2];
                s1 += a[1] + a[3];
                q0 += a[0] * a[0] + a[2] * a[2];
                q1 += a[1] * a[1] + a[3] * a[3];
            }
            atomicAdd(&ssum[col], s0);
            atomicAdd(&ssq[col],  q0);
            atomicAdd(&ssum[col + 1], s1);
            atomicAdd(&ssq[col + 1],  q1);
        }
        __syncthreads();
        if (tid < 128) {
            int col = nbase + tid;
            atomicAdd(&statsOut[col],      (double)ssum[col]);
            atomicAdd(&statsOut[CO + col], (double)ssq[col]);
        }
    }
}

// ---------------- final BN (in-block finalize) + ReLU + transpose ------------------
__global__ void bn_relu_tr_kernel(const float* __restrict__ y,
                                  const double* __restrict__ stats,
                                  const float* __restrict__ g, const float* __restrict__ beta,
                                  float* __restrict__ out) {
    __shared__ float t[32][33];
    __shared__ float sscale[32], sshift[32];
    int b = blockIdx.z;
    int n0 = blockIdx.x * 32, c0 = blockIdx.y * 32;
    if (threadIdx.y == 0) {
        int c = c0 + threadIdx.x;
        double mean = stats[c] * (1.0 / RTOT);
        double var  = stats[CO + c] * (1.0 / RTOT) - mean * mean;
        float sc = g[c] * rsqrtf((float)var + 1e-5f);
        sscale[threadIdx.x] = sc;
        sshift[threadIdx.x] = beta[c] - (float)mean * sc;
    }
    __syncthreads();
    int n = n0 + threadIdx.y, c = c0 + threadIdx.x;
    float v = y[((size_t)b * NPTS + n) * CO + c];
    v = fmaxf(v * sscale[threadIdx.x] + sshift[threadIdx.x], 0.f);
    t[threadIdx.y][threadIdx.x] = v;
    __syncthreads();
    out[((size_t)b * CO + c0 + threadIdx.y) * NPTS + n0 + threadIdx.x] = t[threadIdx.x][threadIdx.y];
}

// ---------------- launch -----------------------------------------------------------
extern "C" void kernel_launch(void* const* d_in, const int* in_sizes, int n_in,
                              void* d_out, int out_size) {
    const float* xyz1    = (const float*)d_in[0];
    const float* xyz2    = (const float*)d_in[1];
    const float* points1 = (const float*)d_in[2];
    const float* points2 = (const float*)d_in[3];
    const float* W1      = (const float*)d_in[4];
    const float* g1      = (const float*)d_in[6];
    const float* beta1   = (const float*)d_in[7];
    const float* W2      = (const float*)d_in[8];
    const float* g2      = (const float*)d_in[10];
    const float* beta2   = (const float*)d_in[11];
    float* out = (float*)d_out;

    float *y, *y2, *Z, *pd;
    unsigned short *Bhi1a, *Blo1a, *Bhi1b, *Blo1b, *Bhi2, *Blo2;
    int *pi;
    double* stats;
    cudaGetSymbolAddress((void**)&y, g_y);
    cudaGetSymbolAddress((void**)&y2, g_y2);
    cudaGetSymbolAddress((void**)&Z, g_Z);
    cudaGetSymbolAddress((void**)&Bhi1a, g_Bhi1a);
    cudaGetSymbolAddress((void**)&Blo1a, g_Blo1a);
    cudaGetSymbolAddress((void**)&Bhi1b, g_Bhi1b);
    cudaGetSymbolAddress((void**)&Blo1b, g_Blo1b);
    cudaGetSymbolAddress((void**)&Bhi2, g_Bhi2);
    cudaGetSymbolAddress((void**)&Blo2, g_Blo2);
    cudaGetSymbolAddress((void**)&pd, g_pd);
    cudaGetSymbolAddress((void**)&pi, g_pi);
    cudaGetSymbolAddress((void**)&stats, g_stats);

    cudaFuncSetAttribute(gemm_kernel<512,0,0,0>, cudaFuncAttributeMaxDynamicSharedMemorySize, SM_TOTAL);
    cudaFuncSetAttribute(gemm_kernel<256,0,1,1>, cudaFuncAttributeMaxDynamicSharedMemorySize, SM_TOTAL);
    cudaFuncSetAttribute(gemm_kernel<256,1,0,1>, cudaFuncAttributeMaxDynamicSharedMemorySize, SM_TOTAL);

    // setup: zero stats + split W1/W2 into fp16 hi/lo
    setup_kernel<<<1024, 256>>>(W1, W2, Bhi1a, Blo1a, Bhi1b, Blo1b, Bhi2, Blo2, stats);

    // 3-NN partials (2 queries per thread)
    three_nn_part_kernel<<<dim3(NPTS / 512, BATCH, NZ), 256>>>(xyz1, xyz2, pd, pi);

    // Z = points2 * W1a^T   (M = 16*1024, K = 512); N split across 2 CTAs
    gemm_kernel<512,0,0,0><<<(BATCH * MPTS / 128) * 2, 256, SM_TOTAL>>>(
        points2, Bhi1a, Blo1a, nullptr, nullptr, nullptr, nullptr, nullptr, nullptr, Z, nullptr);

    // Y1 = points1 * W1b^T + gather3(Z)/3 ; in-prologue NN merge; stats
    gemm_kernel<256,0,1,1><<<(RTOT / 128) * 2, 256, SM_TOTAL>>>(
        points1, Bhi1b, Blo1b, pd, pi, Z, nullptr, nullptr, nullptr, y, stats);

    // Y2 = relu(bn(Y1)) * W2^T ; in-prologue finalize from stats1 ; stats
    gemm_kernel<256,1,0,1><<<(RTOT / 128) * 2, 256, SM_TOTAL>>>(
        y, Bhi2, Blo2, nullptr, nullptr, nullptr, stats, g1, beta1, y2, stats + 512);

    // final BN (in-block finalize from stats2) + ReLU + transpose
    bn_relu_tr_kernel<<<dim3(NPTS / 32, CO / 32, BATCH), dim3(32, 32)>>>(
        y2, stats + 512, g2, beta2, out);
}